// round 2
// baseline (speedup 1.0000x reference)
#include <cuda_runtime.h>

#define NATOMS 1536
#define NSPEC 8
#define HID 64
#define NK 32
#define CUTF 5.0f
#define MAXP ((NATOMS*(NATOMS-1))/2)
#define LOCAL_W (NSPEC*NK)   /* 256 */
#define PI_F 3.14159265358979323846f

// ---- device scratch (no allocations allowed) ----
__device__ float g_acc_pair;                 // pair MLP energy + atom_bias sum
__device__ float g_acc_raw;                  // sum of raw charges
__device__ float g_acc_lr;                   // coulomb sum (unscaled)
__device__ int   g_npairs;
__device__ float g_T[NSPEC*NSPEC*HID];       // species-pair layer1 table (incl b1)
__device__ float g_local[NATOMS*LOCAL_W];    // per-atom basis features
__device__ float g_raw[NATOMS];
__device__ unsigned g_pairs[MAXP];

__device__ __forceinline__ float siluf(float x){ return x/(1.f+__expf(-x)); }

__global__ void k_init(){
    g_acc_pair=0.f; g_acc_raw=0.f; g_acc_lr=0.f; g_npairs=0;
}

// T[si][sj][c] = b1[c] + sum_m (e_si[m]+e_sj[m])*W1[32+m][c] + (e_si[m]*e_sj[m])*W1[64+m][c]
__global__ void k_table(const float* __restrict__ embed, const float* __restrict__ W1,
                        const float* __restrict__ b1){
    int si=blockIdx.x>>3, sj=blockIdx.x&7, c=threadIdx.x;
    float acc=b1[c];
    for(int m=0;m<32;m++){
        float a=embed[si*32+m], b=embed[sj*32+m];
        acc += (a+b)*W1[(32+m)*HID+c];
        acc += (a*b)*W1[(64+m)*HID+c];
    }
    g_T[(si*NSPEC+sj)*HID+c]=acc;
}

// block per atom i: accumulate local basis features + build in-cutoff pair list
__global__ void __launch_bounds__(256) k_local(const float* __restrict__ pos,
                                               const int* __restrict__ species){
    __shared__ float4 sp[NATOMS];     // 24KB
    __shared__ int    ssp[NATOMS];    // 6KB
    __shared__ float  loc[8][LOCAL_W];// 8KB, one copy per warp -> no atomics
    int tid=threadIdx.x;
    int k=tid&31, g=tid>>5;
    int i=blockIdx.x;
    for(int t=tid;t<NATOMS;t+=256){
        sp[t]=make_float4(pos[3*t],pos[3*t+1],pos[3*t+2],0.f);
        ssp[t]=species[t];
    }
    for(int t=tid;t<8*LOCAL_W;t+=256) (&loc[0][0])[t]=0.f;
    __syncthreads();
    float4 pi=sp[i];
    const float C2=-4.0f*1.4426950408889634f;     // -gamma*log2(e)
    const float ck=(CUTF/(NK-1))*(float)k;
    float* myloc = loc[g];
    for(int j=g;j<NATOMS;j+=8){
        if(j==i) continue;
        float4 pj=sp[j];
        float dx=pi.x-pj.x, dy=pi.y-pj.y, dz=pi.z-pj.z;
        float d2=dx*dx+dy*dy+dz*dz+1e-12f;
        if(d2 < CUTF*CUTF){
            float d=sqrtf(d2);
            float cut=0.5f*(__cosf(PI_F*(d*(1.f/CUTF)))+1.f);
            float tt=d-ck;
            myloc[ssp[j]*NK+k] += exp2f(C2*tt*tt)*cut;
            if(j>i && k==0){
                int idx=atomicAdd(&g_npairs,1);
                g_pairs[idx]=((unsigned)i<<16)|(unsigned)j;
            }
        }
    }
    __syncthreads();
    float s=0.f;
    #pragma unroll
    for(int gg=0; gg<8; gg++) s += loc[gg][tid];
    g_local[i*LOCAL_W+tid]=s;
}

// block per atom: charge MLP 289->64->64->1
__global__ void __launch_bounds__(64) k_cmlp(const int* __restrict__ species,
    const float* __restrict__ embed, const float* __restrict__ tc,
    const float* __restrict__ cW1, const float* __restrict__ cb1,
    const float* __restrict__ cW2, const float* __restrict__ cb2,
    const float* __restrict__ cW3, const float* __restrict__ cb3,
    const float* __restrict__ charge_scale, const float* __restrict__ atom_bias){
    __shared__ float x[289];
    __shared__ float h[HID];
    __shared__ float red[HID];
    int i=blockIdx.x, c=threadIdx.x;
    for(int m=c;m<LOCAL_W;m+=64) x[m]=g_local[i*LOCAL_W+m];
    int si=species[i];
    if(c<32) x[LOCAL_W+c]=embed[si*32+c];
    if(c==0) x[288]=tc[0];
    __syncthreads();
    float a=cb1[c];
    for(int m=0;m<289;m++) a += x[m]*cW1[m*HID+c];
    h[c]=siluf(a);
    __syncthreads();
    float b=cb2[c];
    #pragma unroll
    for(int m=0;m<HID;m++) b += h[m]*cW2[m*HID+c];
    red[c]=siluf(b)*cW3[c];
    __syncthreads();
    if(c<32){
        float s=red[c]+red[c+32];
        #pragma unroll
        for(int off=16;off;off>>=1) s+=__shfl_down_sync(0xffffffffu,s,off);
        if(c==0){
            float raw=(s+cb3[0])*charge_scale[0];
            g_raw[i]=raw;
            atomicAdd(&g_acc_raw, raw);
            atomicAdd(&g_acc_pair, atom_bias[si]);
        }
    }
}

__global__ void k_charges(const float* __restrict__ tc, float* __restrict__ out){
    int i=blockIdx.x*blockDim.x+threadIdx.x;
    if(i<NATOMS){
        out[1+i]=g_raw[i]-g_acc_raw*(1.f/NATOMS)+tc[0]*(1.f/NATOMS);
    }
}

// pair-list MLP: 64-thread unit per pair, W1r/W2 columns in registers
__global__ void __launch_bounds__(128) k_pair(const float* __restrict__ pos,
    const int* __restrict__ species, const float* __restrict__ W1,
    const float* __restrict__ b2g, const float* __restrict__ W2,
    const float* __restrict__ W3, const float* __restrict__ b3g){
    __shared__ float sT[NSPEC*NSPEC*HID];  // 16KB
    __shared__ float srbf[2][NK];
    __shared__ float sh1[2][HID];
    __shared__ float spart[2][2];
    int tid=threadIdx.x;
    int u=tid>>6, c=tid&63, lane=tid&31, w=(tid>>5)&1;
    float w1r[NK], w2r[HID];
    #pragma unroll
    for(int k=0;k<NK;k++) w1r[k]=W1[k*HID+c];      // rows 0..31 of W1 (rbf part)
    #pragma unroll
    for(int m=0;m<HID;m++) w2r[m]=W2[m*HID+c];
    float w3  = W3[c];
    float bb2 = b2g[c];
    float b3  = b3g[0];
    for(int t=tid;t<NSPEC*NSPEC*HID;t+=128) sT[t]=g_T[t];
    __syncthreads();
    int np = g_npairs;
    int units = gridDim.x*2;
    int iters = (np + units - 1)/units;
    float eacc = 0.f;
    const float C2=-4.0f*1.4426950408889634f;
    const float dk=CUTF/(NK-1);
    for(int it=0; it<iters; it++){
        int p = it*units + (int)blockIdx.x*2 + u;
        bool act = p < np;
        float cut=0.f; int si=0, sj=0;
        if(act){
            unsigned pr = g_pairs[p];
            int i = (int)(pr>>16), j = (int)(pr&0xffffu);
            float dx=pos[3*i]-pos[3*j], dy=pos[3*i+1]-pos[3*j+1], dz=pos[3*i+2]-pos[3*j+2];
            float d = sqrtf(dx*dx+dy*dy+dz*dz+1e-12f);
            cut = 0.5f*(__cosf(PI_F*(d*(1.f/CUTF)))+1.f);
            si = species[i]; sj = species[j];
            if(c<32){ float tt=d-(float)c*dk; srbf[u][c]=exp2f(C2*tt*tt); }
        }
        __syncthreads();
        if(act){
            float a = sT[(si*NSPEC+sj)*HID+c];
            #pragma unroll
            for(int k=0;k<NK;k++) a += srbf[u][k]*w1r[k];
            sh1[u][c] = siluf(a);
        }
        __syncthreads();
        if(act){
            float b = bb2;
            #pragma unroll
            for(int m=0;m<HID;m++) b += sh1[u][m]*w2r[m];
            float v = siluf(b)*w3;
            #pragma unroll
            for(int off=16;off;off>>=1) v += __shfl_down_sync(0xffffffffu, v, off);
            if(lane==0) spart[u][w]=v;
        }
        __syncthreads();
        if(act && c==0) eacc += (spart[u][0]+spart[u][1]+b3)*cut;
    }
    if(c==0) atomicAdd(&g_acc_pair, eacc);
}

// coulomb over all i<j pairs
__global__ void __launch_bounds__(256) k_coul(const float* __restrict__ pos,
    const float* __restrict__ out, const float* __restrict__ soft_raw){
    __shared__ float4 sp[NATOMS];
    __shared__ float  sq[NATOMS];
    __shared__ float  red[256];
    int tid=threadIdx.x, i=blockIdx.x;
    for(int t=tid;t<NATOMS;t+=256){
        sp[t]=make_float4(pos[3*t],pos[3*t+1],pos[3*t+2],0.f);
        sq[t]=out[1+t];
    }
    __syncthreads();
    float soft=log1pf(expf(soft_raw[0]))+0.001f;
    float s2=soft*soft + 1e-12f;
    float4 pi=sp[i];
    float acc=0.f;
    for(int j=i+1+tid;j<NATOMS;j+=256){
        float4 pj=sp[j];
        float dx=pi.x-pj.x,dy=pi.y-pj.y,dz=pi.z-pj.z;
        acc += sq[j]*rsqrtf(dx*dx+dy*dy+dz*dz+s2);
    }
    red[tid]=acc*sq[i];
    __syncthreads();
    for(int off=128;off;off>>=1){ if(tid<off) red[tid]+=red[tid+off]; __syncthreads(); }
    if(tid==0) atomicAdd(&g_acc_lr, red[0]);
}

__global__ void k_final(const float* __restrict__ cs, float* __restrict__ out){
    out[0]=g_acc_pair + cs[0]*g_acc_lr;
}

extern "C" void kernel_launch(void* const* d_in, const int* in_sizes, int n_in,
                              void* d_out, int out_size){
    const int*   species      =(const int*)  d_in[0];
    const float* pos          =(const float*)d_in[1];
    const float* tc           =(const float*)d_in[2];
    const float* embed        =(const float*)d_in[3];
    const float* W1           =(const float*)d_in[4];
    const float* b1           =(const float*)d_in[5];
    const float* W2           =(const float*)d_in[6];
    const float* b2           =(const float*)d_in[7];
    const float* W3           =(const float*)d_in[8];
    const float* b3           =(const float*)d_in[9];
    const float* atom_bias    =(const float*)d_in[10];
    const float* cW1          =(const float*)d_in[11];
    const float* cb1          =(const float*)d_in[12];
    const float* cW2          =(const float*)d_in[13];
    const float* cb2          =(const float*)d_in[14];
    const float* cW3          =(const float*)d_in[15];
    const float* cb3          =(const float*)d_in[16];
    const float* charge_scale =(const float*)d_in[17];
    const float* coulomb_scale=(const float*)d_in[18];
    const float* soft_raw     =(const float*)d_in[19];
    float* out=(float*)d_out;

    k_init   <<<1,1>>>();
    k_table  <<<64,64>>>(embed,W1,b1);
    k_local  <<<NATOMS,256>>>(pos,species);
    k_cmlp   <<<NATOMS,64>>>(species,embed,tc,cW1,cb1,cW2,cb2,cW3,cb3,charge_scale,atom_bias);
    k_charges<<<6,256>>>(tc,out);
    k_pair   <<<592,128>>>(pos,species,W1,b2,W2,W3,b3);
    k_coul   <<<NATOMS,256>>>(pos,out,soft_raw);
    k_final  <<<1,1>>>(coulomb_scale,out);
}

// round 3
// speedup vs baseline: 1.2363x; 1.2363x over previous
#include <cuda_runtime.h>

#define NATOMS 1536
#define NSPEC 8
#define HID 64
#define NK 32
#define CUTF 5.0f
#define MAXP ((NATOMS*(NATOMS-1))/2)
#define LOCAL_W (NSPEC*NK)   /* 256 */
#define PI_F 3.14159265358979323846f

// ---- device scratch ----
__device__ float g_acc_pair;
__device__ float g_acc_raw;
__device__ float g_acc_lr;
__device__ int   g_npairs;
__device__ float g_T[NSPEC*NSPEC*HID];
__device__ float g_local[NATOMS*LOCAL_W];
__device__ float g_raw[NATOMS];
__device__ unsigned g_pairs[MAXP];

__device__ __forceinline__ float siluf(float x){ return x/(1.f+__expf(-x)); }

// ---- k_table: species-pair layer1 table + global init ----
__global__ void k_table(const float* __restrict__ embed, const float* __restrict__ W1,
                        const float* __restrict__ b1){
    if(blockIdx.x==0 && threadIdx.x==0){
        g_acc_pair=0.f; g_acc_raw=0.f; g_acc_lr=0.f; g_npairs=0;
    }
    int si=blockIdx.x>>3, sj=blockIdx.x&7, c=threadIdx.x;
    float acc=b1[c];
    for(int m=0;m<32;m++){
        float a=embed[si*32+m], b=embed[sj*32+m];
        acc += (a+b)*W1[(32+m)*HID+c];
        acc += (a*b)*W1[(64+m)*HID+c];
    }
    g_T[(si*NSPEC+sj)*HID+c]=acc;
}

// ---- k_local: basis features + buffered pair list (1 atomic per block) ----
__global__ void __launch_bounds__(256) k_local(const float* __restrict__ pos,
                                               const int* __restrict__ species){
    __shared__ float4 sp[NATOMS];       // 24KB
    __shared__ int    ssp[NATOMS];      // 6KB
    __shared__ float  loc[8][LOCAL_W];  // 8KB
    __shared__ unsigned short plist[8][192]; // 3KB
    __shared__ int pcnt[8];
    __shared__ int poff[8];
    __shared__ int pbase;
    int tid=threadIdx.x;
    int k=tid&31, g=tid>>5;
    int i=blockIdx.x;
    for(int t=tid;t<NATOMS;t+=256){
        sp[t]=make_float4(pos[3*t],pos[3*t+1],pos[3*t+2],0.f);
        ssp[t]=species[t];
    }
    for(int t=tid;t<8*LOCAL_W;t+=256) (&loc[0][0])[t]=0.f;
    __syncthreads();
    float4 pi=sp[i];
    const float C2=-4.0f*1.4426950408889634f;
    const float ck=(CUTF/(NK-1))*(float)k;
    float* myloc = loc[g];
    int cnt=0;   // warp-uniform
    for(int j=g;j<NATOMS;j+=8){
        if(j==i) continue;
        float4 pj=sp[j];
        float dx=pi.x-pj.x, dy=pi.y-pj.y, dz=pi.z-pj.z;
        float d2=dx*dx+dy*dy+dz*dz+1e-12f;
        if(d2 < CUTF*CUTF){
            float d=sqrtf(d2);
            float cut=0.5f*(__cosf(PI_F*(d*(1.f/CUTF)))+1.f);
            float tt=d-ck;
            myloc[ssp[j]*NK+k] += exp2f(C2*tt*tt)*cut;
            if(j>i){
                if(k==0) plist[g][cnt]=(unsigned short)j;
                cnt++;
            }
        }
    }
    if(k==0) pcnt[g]=cnt;
    __syncthreads();
    if(tid==0){
        int tot=0;
        #pragma unroll
        for(int gg=0;gg<8;gg++){ poff[gg]=tot; tot+=pcnt[gg]; }
        pbase = tot ? atomicAdd(&g_npairs, tot) : 0;
    }
    __syncthreads();
    {
        int n=pcnt[g], base=pbase+poff[g];
        unsigned hi=((unsigned)i)<<16;
        for(int t=k;t<n;t+=32) g_pairs[base+t]= hi | (unsigned)plist[g][t];
    }
    float s=0.f;
    #pragma unroll
    for(int gg=0; gg<8; gg++) s += loc[gg][tid];
    g_local[i*LOCAL_W+tid]=s;
}

// ---- k_cmlp: 16-atom tile fused charge MLP ----
#define CT_M 16
__global__ void __launch_bounds__(256) k_cmlp(const int* __restrict__ species,
    const float* __restrict__ embed, const float* __restrict__ tc,
    const float* __restrict__ cW1, const float* __restrict__ cb1,
    const float* __restrict__ cW2, const float* __restrict__ cb2,
    const float* __restrict__ cW3, const float* __restrict__ cb3,
    const float* __restrict__ charge_scale, const float* __restrict__ atom_bias){
    __shared__ float xs[CT_M][292];   // 292*4 = 1168B rows (16B multiple)
    __shared__ float hs[CT_M][64];
    __shared__ float vs[CT_M][64];
    int tid=threadIdx.x, c=tid&63, sub=tid>>6;
    int base=blockIdx.x*CT_M;
    // assemble x tile
    for(int idx=tid; idx<CT_M*256; idx+=256){
        int a=idx>>8, m=idx&255;
        xs[a][m]=g_local[(base+a)*LOCAL_W+m];
    }
    for(int idx=tid; idx<CT_M*32; idx+=256){
        int a=idx>>5, m=idx&31;
        xs[a][256+m]=embed[species[base+a]*32+m];
    }
    if(tid<CT_M) xs[tid][288]=tc[0];
    __syncthreads();
    int a0=sub*4;
    float acc[4];
    {
        float b=cb1[c];
        acc[0]=b; acc[1]=b; acc[2]=b; acc[3]=b;
    }
    for(int m=0;m<288;m+=4){
        float w0=__ldg(&cW1[(m+0)*HID+c]);
        float w1=__ldg(&cW1[(m+1)*HID+c]);
        float w2=__ldg(&cW1[(m+2)*HID+c]);
        float w3=__ldg(&cW1[(m+3)*HID+c]);
        #pragma unroll
        for(int aa=0;aa<4;aa++){
            float4 x=*(const float4*)&xs[a0+aa][m];
            acc[aa]+=x.x*w0+x.y*w1+x.z*w2+x.w*w3;
        }
    }
    {
        float w=__ldg(&cW1[288*HID+c]);
        #pragma unroll
        for(int aa=0;aa<4;aa++) acc[aa]+=xs[a0+aa][288]*w;
    }
    #pragma unroll
    for(int aa=0;aa<4;aa++) hs[a0+aa][c]=siluf(acc[aa]);
    __syncthreads();
    float acc2[4];
    {
        float b=cb2[c];
        acc2[0]=b; acc2[1]=b; acc2[2]=b; acc2[3]=b;
    }
    for(int m=0;m<HID;m+=4){
        float w0=__ldg(&cW2[(m+0)*HID+c]);
        float w1=__ldg(&cW2[(m+1)*HID+c]);
        float w2=__ldg(&cW2[(m+2)*HID+c]);
        float w3=__ldg(&cW2[(m+3)*HID+c]);
        #pragma unroll
        for(int aa=0;aa<4;aa++){
            float4 h=*(const float4*)&hs[a0+aa][m];
            acc2[aa]+=h.x*w0+h.y*w1+h.z*w2+h.w*w3;
        }
    }
    float w3v=__ldg(&cW3[c]);
    #pragma unroll
    for(int aa=0;aa<4;aa++) vs[a0+aa][c]=siluf(acc2[aa])*w3v;
    __syncthreads();
    if(tid<CT_M){
        float s=0.f;
        const float4* v4=(const float4*)vs[tid];
        #pragma unroll
        for(int t=0;t<16;t++){ float4 v=v4[t]; s+=v.x+v.y+v.z+v.w; }
        float raw=(s+cb3[0])*charge_scale[0];
        g_raw[base+tid]=raw;
        float ab=atom_bias[species[base+tid]];
        #pragma unroll
        for(int off=8;off;off>>=1){
            raw+=__shfl_down_sync(0x0000ffffu,raw,off,16);
            ab +=__shfl_down_sync(0x0000ffffu,ab ,off,16);
        }
        if(tid==0){
            atomicAdd(&g_acc_raw, raw);
            atomicAdd(&g_acc_pair, ab);
        }
    }
}

// ---- k_pair: compacted pair MLP, 2 units of 64 per block ----
__global__ void __launch_bounds__(128) k_pair(const float* __restrict__ pos,
    const int* __restrict__ species, const float* __restrict__ W1,
    const float* __restrict__ b2g, const float* __restrict__ W2,
    const float* __restrict__ W3, const float* __restrict__ b3g){
    __shared__ float sT[NSPEC*NSPEC*HID];  // 16KB
    __shared__ float srbf[2][32];
    __shared__ float sh1[2][64];
    int tid=threadIdx.x;
    int u=tid>>6, c=tid&63, lane=tid&31;
    float w1r[NK], w2r[HID];
    #pragma unroll
    for(int k=0;k<NK;k++) w1r[k]=W1[k*HID+c];
    #pragma unroll
    for(int m=0;m<HID;m++) w2r[m]=W2[m*HID+c];
    float w3  = W3[c];
    float bb2 = b2g[c];
    float b3  = b3g[0];
    {
        const float4* src=(const float4*)g_T;
        float4* dst=(float4*)sT;
        for(int t=tid;t<NSPEC*NSPEC*HID/4;t+=128) dst[t]=src[t];
    }
    __syncthreads();
    int np = g_npairs;
    int units = gridDim.x*2;
    int iters = (np + units - 1)/units;
    float eacc = 0.f;
    const float C2=-4.0f*1.4426950408889634f;
    const float dk=CUTF/(NK-1);
    for(int it=0; it<iters; it++){
        int p = it*units + (int)blockIdx.x*2 + u;
        bool act = p < np;
        float cut=0.f; int si=0, sj=0;
        if(act){
            unsigned pr = __ldg(&g_pairs[p]);
            int i = (int)(pr>>16), j = (int)(pr&0xffffu);
            float dx=__ldg(&pos[3*i])-__ldg(&pos[3*j]);
            float dy=__ldg(&pos[3*i+1])-__ldg(&pos[3*j+1]);
            float dz=__ldg(&pos[3*i+2])-__ldg(&pos[3*j+2]);
            float d = sqrtf(dx*dx+dy*dy+dz*dz+1e-12f);
            cut = 0.5f*(__cosf(PI_F*(d*(1.f/CUTF)))+1.f);
            si = __ldg(&species[i]); sj = __ldg(&species[j]);
            if(c<32){ float t2=d-(float)c*dk; srbf[u][c]=exp2f(C2*t2*t2); }
        }
        __syncthreads();    // srbf ready; prev iter's sh1 fully consumed
        if(act){
            float a = sT[(si*NSPEC+sj)*HID+c];
            const float4* r4=(const float4*)srbf[u];
            #pragma unroll
            for(int t=0;t<8;t++){
                float4 r=r4[t];
                a += r.x*w1r[4*t] + r.y*w1r[4*t+1] + r.z*w1r[4*t+2] + r.w*w1r[4*t+3];
            }
            sh1[u][c] = siluf(a);
        }
        __syncthreads();    // sh1 ready
        if(act){
            float b = bb2;
            const float4* h4=(const float4*)sh1[u];
            #pragma unroll
            for(int t=0;t<16;t++){
                float4 h=h4[t];
                b += h.x*w2r[4*t] + h.y*w2r[4*t+1] + h.z*w2r[4*t+2] + h.w*w2r[4*t+3];
            }
            float v = siluf(b)*w3;
            #pragma unroll
            for(int off=16;off;off>>=1) v += __shfl_down_sync(0xffffffffu, v, off);
            if(lane==0){
                eacc += v*cut;                  // per-warp partial (cols 0-31 / 32-63)
                if(c==0) eacc += b3*cut;        // bias once per pair
            }
        }
    }
    if(lane==0) atomicAdd(&g_acc_pair, eacc);
}

// ---- k_coul: tiled triangle + charge normalization/output ----
#define NT (NATOMS/256)
__global__ void __launch_bounds__(256) k_coul(const float* __restrict__ pos,
    const float* __restrict__ tc, const float* __restrict__ soft_raw,
    float* __restrict__ out){
    __shared__ float4 sp[256];
    __shared__ float  sq[256];
    __shared__ float  red[256];
    int b=blockIdx.x;
    int bi=0;
    {   int bb=b;
        while(bb >= NT-bi){ bb-=NT-bi; bi++; }
        b=bb;
    }
    int bj=bi+b;
    int t=threadIdx.x;
    float mu = g_acc_raw*(1.f/NATOMS);
    float qadd = tc[0]*(1.f/NATOMS) - mu;
    int i = bi*256+t;
    float qi = g_raw[i]+qadd;
    float4 piv = make_float4(pos[3*i],pos[3*i+1],pos[3*i+2],0.f);
    {
        int j = bj*256+t;
        sp[t]=make_float4(pos[3*j],pos[3*j+1],pos[3*j+2],0.f);
        sq[t]=g_raw[j]+qadd;
    }
    __syncthreads();
    float soft=log1pf(__expf(soft_raw[0]))+0.001f;
    float s2=soft*soft+1e-12f;
    float acc=0.f;
    if(bi==bj){
        out[1+i]=qi;
        for(int jj=t+1;jj<256;jj++){
            float4 pj=sp[jj];
            float dx=piv.x-pj.x,dy=piv.y-pj.y,dz=piv.z-pj.z;
            acc += sq[jj]*rsqrtf(dx*dx+dy*dy+dz*dz+s2);
        }
    } else {
        for(int jj=0;jj<256;jj++){
            float4 pj=sp[jj];
            float dx=piv.x-pj.x,dy=piv.y-pj.y,dz=piv.z-pj.z;
            acc += sq[jj]*rsqrtf(dx*dx+dy*dy+dz*dz+s2);
        }
    }
    red[t]=acc*qi;
    __syncthreads();
    for(int off=128;off;off>>=1){ if(t<off) red[t]+=red[t+off]; __syncthreads(); }
    if(t==0) atomicAdd(&g_acc_lr, red[0]);
}

__global__ void k_final(const float* __restrict__ cs, float* __restrict__ out){
    out[0]=g_acc_pair + cs[0]*g_acc_lr;
}

extern "C" void kernel_launch(void* const* d_in, const int* in_sizes, int n_in,
                              void* d_out, int out_size){
    const int*   species      =(const int*)  d_in[0];
    const float* pos          =(const float*)d_in[1];
    const float* tc           =(const float*)d_in[2];
    const float* embed        =(const float*)d_in[3];
    const float* W1           =(const float*)d_in[4];
    const float* b1           =(const float*)d_in[5];
    const float* W2           =(const float*)d_in[6];
    const float* b2           =(const float*)d_in[7];
    const float* W3           =(const float*)d_in[8];
    const float* b3           =(const float*)d_in[9];
    const float* atom_bias    =(const float*)d_in[10];
    const float* cW1          =(const float*)d_in[11];
    const float* cb1          =(const float*)d_in[12];
    const float* cW2          =(const float*)d_in[13];
    const float* cb2          =(const float*)d_in[14];
    const float* cW3          =(const float*)d_in[15];
    const float* cb3          =(const float*)d_in[16];
    const float* charge_scale =(const float*)d_in[17];
    const float* coulomb_scale=(const float*)d_in[18];
    const float* soft_raw     =(const float*)d_in[19];
    float* out=(float*)d_out;

    k_table <<<64,64>>>(embed,W1,b1);
    k_local <<<NATOMS,256>>>(pos,species);
    k_cmlp  <<<NATOMS/CT_M,256>>>(species,embed,tc,cW1,cb1,cW2,cb2,cW3,cb3,charge_scale,atom_bias);
    k_pair  <<<592,128>>>(pos,species,W1,b2,W2,W3,b3);
    k_coul  <<<NT*(NT+1)/2,256>>>(pos,tc,soft_raw,out);
    k_final <<<1,1>>>(coulomb_scale,out);
}

// round 4
// speedup vs baseline: 1.6596x; 1.3424x over previous
#include <cuda_runtime.h>

typedef unsigned long long ull;

#define NATOMS 1536
#define NSPEC 8
#define HID 64
#define NK 32
#define CUTF 5.0f
#define MAXP ((NATOMS*(NATOMS-1))/2)
#define LOCAL_W (NSPEC*NK)   /* 256 */
#define PI_F 3.14159265358979323846f
#define LOG2E 1.4426950408889634f

// ---- device scratch ----
__device__ float g_acc_pair;
__device__ float g_acc_raw;
__device__ float g_acc_lr;
__device__ int   g_npairs;
__device__ float g_T[NSPEC*NSPEC*HID];
__device__ float g_local[NATOMS*LOCAL_W];
__device__ float g_raw[NATOMS];
__device__ float4 g_pos4[NATOMS];
__device__ unsigned g_pairs[MAXP];

__device__ __forceinline__ float siluf(float x){ return __fdividef(x, 1.f+__expf(-x)); }

__device__ __forceinline__ ull pk2(float lo, float hi){
    ull r; asm("mov.b64 %0,{%1,%2};" : "=l"(r) : "f"(lo), "f"(hi)); return r;
}
__device__ __forceinline__ void upk2(ull v, float& lo, float& hi){
    asm("mov.b64 {%0,%1},%2;" : "=f"(lo), "=f"(hi) : "l"(v));
}
__device__ __forceinline__ void fma2(ull& d, ull a, ull b){
    asm("fma.rn.f32x2 %0,%1,%2,%0;" : "+l"(d) : "l"(a), "l"(b));
}

// ---- k_table: species-pair layer1 table + init + pos4 staging ----
__global__ void k_table(const float* __restrict__ pos,
                        const float* __restrict__ embed, const float* __restrict__ W1,
                        const float* __restrict__ b1){
    if(blockIdx.x==0 && threadIdx.x==0){
        g_acc_pair=0.f; g_acc_raw=0.f; g_acc_lr=0.f; g_npairs=0;
    }
    int t=blockIdx.x*64+threadIdx.x;
    if(t<NATOMS) g_pos4[t]=make_float4(pos[3*t],pos[3*t+1],pos[3*t+2],0.f);
    int si=blockIdx.x>>3, sj=blockIdx.x&7, c=threadIdx.x;
    float acc=b1[c];
    for(int m=0;m<32;m++){
        float a=embed[si*32+m], b=embed[sj*32+m];
        acc += (a+b)*W1[(32+m)*HID+c];
        acc += (a*b)*W1[(64+m)*HID+c];
    }
    g_T[(si*NSPEC+sj)*HID+c]=acc;
}

// ---- k_local: 4 atoms per block, 2 warps per atom ----
#define PLCAP 448
__global__ void __launch_bounds__(256) k_local(const float* __restrict__ pos,
                                               const int* __restrict__ species){
    __shared__ float4 sp[NATOMS];            // 24KB
    __shared__ unsigned char ssp[NATOMS];    // 1.5KB
    __shared__ float loc[4][2][LOCAL_W];     // 8KB
    __shared__ unsigned short plist[8][PLCAP]; // 7KB
    __shared__ int pcnt[8];
    __shared__ int poff[8];
    __shared__ int pbase;
    int tid=threadIdx.x, lane=tid&31, w=tid>>5;
    int a=w>>1, half=w&1;
    int i=blockIdx.x*4+a;
    for(int t=tid;t<NATOMS;t+=256){
        sp[t]=make_float4(pos[3*t],pos[3*t+1],pos[3*t+2],0.f);
        ssp[t]=(unsigned char)species[t];
    }
    for(int t=tid;t<4*2*LOCAL_W;t+=256) (&loc[0][0][0])[t]=0.f;
    __syncthreads();
    float4 pi=sp[i];
    const float C2=-4.0f*LOG2E;
    const float ck=(CUTF/(NK-1))*(float)lane;
    float* myloc = loc[a][half];
    int cnt=0;   // warp-uniform
    for(int j=half;j<NATOMS;j+=2){
        if(j==i) continue;
        float4 pj=sp[j];
        float dx=pi.x-pj.x, dy=pi.y-pj.y, dz=pi.z-pj.z;
        float d2=dx*dx+dy*dy+dz*dz+1e-12f;
        if(d2 < CUTF*CUTF){
            float d=sqrtf(d2);
            float cut=0.5f*(__cosf(PI_F*(d*(1.f/CUTF)))+1.f);
            float tt=d-ck;
            myloc[ssp[j]*NK+lane] += exp2f(C2*tt*tt)*cut;
            if(j>i){
                if(lane==0) plist[w][cnt]=(unsigned short)j;
                cnt++;
            }
        }
    }
    if(lane==0) pcnt[w]=cnt;
    __syncthreads();
    if(tid==0){
        int tot=0;
        #pragma unroll
        for(int gg=0;gg<8;gg++){ poff[gg]=tot; tot+=pcnt[gg]; }
        pbase = tot ? atomicAdd(&g_npairs, tot) : 0;
    }
    __syncthreads();
    {
        int n=pcnt[w], base=pbase+poff[w];
        unsigned hi=((unsigned)i)<<11;
        unsigned sihi=((unsigned)ssp[i])<<3;
        for(int t=lane;t<n;t+=32){
            unsigned j=plist[w][t];
            g_pairs[base+t]= ((sihi|(unsigned)ssp[j])<<22) | hi | j;
        }
    }
    for(int t=tid;t<4*LOCAL_W;t+=256){
        int aa=t>>8, m=t&255;
        g_local[(blockIdx.x*4+aa)*LOCAL_W+m]=loc[aa][0][m]+loc[aa][1][m];
    }
}

// ---- k_cmlp: 16-atom tile fused charge MLP ----
#define CT_M 16
__global__ void __launch_bounds__(256) k_cmlp(const int* __restrict__ species,
    const float* __restrict__ embed, const float* __restrict__ tc,
    const float* __restrict__ cW1, const float* __restrict__ cb1,
    const float* __restrict__ cW2, const float* __restrict__ cb2,
    const float* __restrict__ cW3, const float* __restrict__ cb3,
    const float* __restrict__ charge_scale, const float* __restrict__ atom_bias){
    __shared__ float xs[CT_M][292];
    __shared__ float hs[CT_M][64];
    __shared__ float vs[CT_M][64];
    int tid=threadIdx.x, c=tid&63, sub=tid>>6;
    int base=blockIdx.x*CT_M;
    for(int idx=tid; idx<CT_M*256; idx+=256){
        int a=idx>>8, m=idx&255;
        xs[a][m]=g_local[(base+a)*LOCAL_W+m];
    }
    for(int idx=tid; idx<CT_M*32; idx+=256){
        int a=idx>>5, m=idx&31;
        xs[a][256+m]=embed[species[base+a]*32+m];
    }
    if(tid<CT_M) xs[tid][288]=tc[0];
    __syncthreads();
    int a0=sub*4;
    float acc[4];
    { float b=cb1[c]; acc[0]=b; acc[1]=b; acc[2]=b; acc[3]=b; }
    for(int m=0;m<288;m+=4){
        float w0=__ldg(&cW1[(m+0)*HID+c]);
        float w1=__ldg(&cW1[(m+1)*HID+c]);
        float w2=__ldg(&cW1[(m+2)*HID+c]);
        float w3=__ldg(&cW1[(m+3)*HID+c]);
        #pragma unroll
        for(int aa=0;aa<4;aa++){
            float4 x=*(const float4*)&xs[a0+aa][m];
            acc[aa]+=x.x*w0+x.y*w1+x.z*w2+x.w*w3;
        }
    }
    {
        float w=__ldg(&cW1[288*HID+c]);
        #pragma unroll
        for(int aa=0;aa<4;aa++) acc[aa]+=xs[a0+aa][288]*w;
    }
    #pragma unroll
    for(int aa=0;aa<4;aa++) hs[a0+aa][c]=siluf(acc[aa]);
    __syncthreads();
    float acc2[4];
    { float b=cb2[c]; acc2[0]=b; acc2[1]=b; acc2[2]=b; acc2[3]=b; }
    for(int m=0;m<HID;m+=4){
        float w0=__ldg(&cW2[(m+0)*HID+c]);
        float w1=__ldg(&cW2[(m+1)*HID+c]);
        float w2=__ldg(&cW2[(m+2)*HID+c]);
        float w3=__ldg(&cW2[(m+3)*HID+c]);
        #pragma unroll
        for(int aa=0;aa<4;aa++){
            float4 h=*(const float4*)&hs[a0+aa][m];
            acc2[aa]+=h.x*w0+h.y*w1+h.z*w2+h.w*w3;
        }
    }
    float w3v=__ldg(&cW3[c]);
    #pragma unroll
    for(int aa=0;aa<4;aa++) vs[a0+aa][c]=siluf(acc2[aa])*w3v;
    __syncthreads();
    if(tid<CT_M){
        float s=0.f;
        const float4* v4=(const float4*)vs[tid];
        #pragma unroll
        for(int t=0;t<16;t++){ float4 v=v4[t]; s+=v.x+v.y+v.z+v.w; }
        float raw=(s+cb3[0])*charge_scale[0];
        g_raw[base+tid]=raw;
        float ab=atom_bias[species[base+tid]];
        #pragma unroll
        for(int off=8;off;off>>=1){
            raw+=__shfl_down_sync(0x0000ffffu,raw,off,16);
            ab +=__shfl_down_sync(0x0000ffffu,ab ,off,16);
        }
        if(tid==0){
            atomicAdd(&g_acc_raw, raw);
            atomicAdd(&g_acc_pair, ab);
        }
    }
}

// ---- k_pair: lane=pair, f32x2 packed MLP, no inner barriers ----
__global__ void __launch_bounds__(128,3) k_pair(
    const float* __restrict__ W1, const float* __restrict__ b2g,
    const float* __restrict__ W2, const float* __restrict__ W3,
    const float* __restrict__ b3g){
    __shared__ float sW1[NK*HID];      // 8KB  (row k: 64 ch, packed pairs contiguous)
    __shared__ float sW2[HID*HID];     // 16KB
    __shared__ float sT[NSPEC*NSPEC*HID]; // 16KB
    __shared__ float sW3[HID];
    __shared__ ull   sB2[HID/2];
    int tid=threadIdx.x;
    for(int t=tid;t<NK*HID/4;t+=128)  ((float4*)sW1)[t]=((const float4*)W1)[t];
    for(int t=tid;t<HID*HID/4;t+=128) ((float4*)sW2)[t]=((const float4*)W2)[t];
    for(int t=tid;t<NSPEC*NSPEC*HID/4;t+=128) ((float4*)sT)[t]=((const float4*)g_T)[t];
    if(tid<HID)   sW3[tid]=W3[tid];
    if(tid<HID/2) sB2[tid]=pk2(b2g[2*tid],b2g[2*tid+1]);
    __syncthreads();
    float b3=b3g[0];
    int np=g_npairs;
    int lane=tid&31;
    int gw=(blockIdx.x*128+tid)>>5;
    int nw=(gridDim.x*128)>>5;
    const float C2=-4.0f*LOG2E;
    const float dk=CUTF/(NK-1);
    float eacc=0.f;
    for(int base=gw*32; base<np; base+=nw*32){
        int p=base+lane;
        bool act = p<np;
        unsigned pr = __ldg(&g_pairs[act? p : (np-1)]);
        int spidx = (int)(pr>>22);
        int i=(int)((pr>>11)&2047u), j=(int)(pr&2047u);
        float4 pi=__ldg(&g_pos4[i]);
        float4 pj=__ldg(&g_pos4[j]);
        float dx=pi.x-pj.x, dy=pi.y-pj.y, dz=pi.z-pj.z;
        float d=sqrtf(dx*dx+dy*dy+dz*dz+1e-12f);
        float cut = act ? 0.5f*(__cosf(PI_F*(d*(1.f/CUTF)))+1.f) : 0.f;
        // ---- layer 1: acc[q] = channels (2q, 2q+1), init from T row ----
        ull acc[32];
        const float4* Tr=(const float4*)&sT[spidx*HID];
        #pragma unroll
        for(int q=0;q<16;q++){
            float4 t=Tr[q];
            acc[2*q]=pk2(t.x,t.y); acc[2*q+1]=pk2(t.z,t.w);
        }
        #pragma unroll 4
        for(int k=0;k<NK;k++){
            float t=d-(float)k*dk;
            float r=exp2f(C2*t*t);
            ull rd=pk2(r,r);
            const ulonglong2* wr=(const ulonglong2*)&sW1[k*HID];
            #pragma unroll
            for(int q=0;q<16;q++){
                ulonglong2 wv=wr[q];
                fma2(acc[2*q],   rd, wv.x);
                fma2(acc[2*q+1], rd, wv.y);
            }
        }
        // ---- layer 2 fused with silu of layer 1 ----
        ull acc2[32];
        #pragma unroll
        for(int q=0;q<32;q++) acc2[q]=sB2[q];
        #pragma unroll
        for(int mq=0;mq<32;mq++){
            float h0,h1; upk2(acc[mq],h0,h1);
            h0=siluf(h0); h1=siluf(h1);
            ull hd0=pk2(h0,h0), hd1=pk2(h1,h1);
            const ulonglong2* wr0=(const ulonglong2*)&sW2[(2*mq)*HID];
            const ulonglong2* wr1=(const ulonglong2*)&sW2[(2*mq+1)*HID];
            #pragma unroll
            for(int q=0;q<16;q++){
                ulonglong2 w0=wr0[q];
                ulonglong2 w1=wr1[q];
                fma2(acc2[2*q],   hd0, w0.x);
                fma2(acc2[2*q+1], hd0, w0.y);
                fma2(acc2[2*q],   hd1, w1.x);
                fma2(acc2[2*q+1], hd1, w1.y);
            }
        }
        // ---- epilogue: silu + W3 dot + b3, gated by cut ----
        float e=b3;
        #pragma unroll
        for(int q=0;q<32;q++){
            float a,b; upk2(acc2[q],a,b);
            e += siluf(a)*sW3[2*q] + siluf(b)*sW3[2*q+1];
        }
        eacc += e*cut;
    }
    #pragma unroll
    for(int off=16;off;off>>=1) eacc += __shfl_down_sync(0xffffffffu, eacc, off);
    if(lane==0) atomicAdd(&g_acc_pair, eacc);
}

// ---- k_coul: tiled triangle + charge normalization/output ----
#define NT (NATOMS/256)
__global__ void __launch_bounds__(256) k_coul(const float* __restrict__ pos,
    const float* __restrict__ tc, const float* __restrict__ soft_raw,
    float* __restrict__ out){
    __shared__ float4 sp[256];
    __shared__ float  sq[256];
    __shared__ float  red[256];
    int b=blockIdx.x;
    int bi=0;
    {   int bb=b;
        while(bb >= NT-bi){ bb-=NT-bi; bi++; }
        b=bb;
    }
    int bj=bi+b;
    int t=threadIdx.x;
    float mu = g_acc_raw*(1.f/NATOMS);
    float qadd = tc[0]*(1.f/NATOMS) - mu;
    int i = bi*256+t;
    float qi = g_raw[i]+qadd;
    float4 piv = make_float4(pos[3*i],pos[3*i+1],pos[3*i+2],0.f);
    {
        int j = bj*256+t;
        sp[t]=make_float4(pos[3*j],pos[3*j+1],pos[3*j+2],0.f);
        sq[t]=g_raw[j]+qadd;
    }
    __syncthreads();
    float soft=log1pf(__expf(soft_raw[0]))+0.001f;
    float s2=soft*soft+1e-12f;
    float acc=0.f;
    if(bi==bj){
        out[1+i]=qi;
        for(int jj=t+1;jj<256;jj++){
            float4 pj=sp[jj];
            float dx=piv.x-pj.x,dy=piv.y-pj.y,dz=piv.z-pj.z;
            acc += sq[jj]*rsqrtf(dx*dx+dy*dy+dz*dz+s2);
        }
    } else {
        for(int jj=0;jj<256;jj++){
            float4 pj=sp[jj];
            float dx=piv.x-pj.x,dy=piv.y-pj.y,dz=piv.z-pj.z;
            acc += sq[jj]*rsqrtf(dx*dx+dy*dy+dz*dz+s2);
        }
    }
    red[t]=acc*qi;
    __syncthreads();
    for(int off=128;off;off>>=1){ if(t<off) red[t]+=red[t+off]; __syncthreads(); }
    if(t==0) atomicAdd(&g_acc_lr, red[0]);
}

__global__ void k_final(const float* __restrict__ cs, float* __restrict__ out){
    out[0]=g_acc_pair + cs[0]*g_acc_lr;
}

extern "C" void kernel_launch(void* const* d_in, const int* in_sizes, int n_in,
                              void* d_out, int out_size){
    const int*   species      =(const int*)  d_in[0];
    const float* pos          =(const float*)d_in[1];
    const float* tc           =(const float*)d_in[2];
    const float* embed        =(const float*)d_in[3];
    const float* W1           =(const float*)d_in[4];
    const float* b1           =(const float*)d_in[5];
    const float* W2           =(const float*)d_in[6];
    const float* b2           =(const float*)d_in[7];
    const float* W3           =(const float*)d_in[8];
    const float* b3           =(const float*)d_in[9];
    const float* atom_bias    =(const float*)d_in[10];
    const float* cW1          =(const float*)d_in[11];
    const float* cb1          =(const float*)d_in[12];
    const float* cW2          =(const float*)d_in[13];
    const float* cb2          =(const float*)d_in[14];
    const float* cW3          =(const float*)d_in[15];
    const float* cb3          =(const float*)d_in[16];
    const float* charge_scale =(const float*)d_in[17];
    const float* coulomb_scale=(const float*)d_in[18];
    const float* soft_raw     =(const float*)d_in[19];
    float* out=(float*)d_out;

    k_table <<<64,64>>>(pos,embed,W1,b1);
    k_local <<<NATOMS/4,256>>>(pos,species);
    k_cmlp  <<<NATOMS/CT_M,256>>>(species,embed,tc,cW1,cb1,cW2,cb2,cW3,cb3,charge_scale,atom_bias);
    k_pair  <<<444,128>>>(W1,b2,W2,W3,b3);
    k_coul  <<<NT*(NT+1)/2,256>>>(pos,tc,soft_raw,out);
    k_final <<<1,1>>>(coulomb_scale,out);
}